// round 4
// baseline (speedup 1.0000x reference)
#include <cuda_runtime.h>
#include <cuda_bf16.h>
#include <cstdint>

#define CH   512
#define HW   4096
#define SCALE (1.0e6f / 33554432.0f)

__device__ __align__(16) float g_G[CH * CH];     // 1 MB gram (scaled by 1/2^20)
__device__ __align__(16) float g_S[CH * CH];     // 1 MB S matrix
__device__ float g_sumT2;

// ---------------------------------------------------------------------------
// Kernel 0: zero G / sumT2 / out
// ---------------------------------------------------------------------------
__global__ void __launch_bounds__(256) k_zero(float* __restrict__ out) {
    const int gi = blockIdx.x * 256 + threadIdx.x;    // 65536 float4's
    reinterpret_cast<float4*>(g_G)[gi] = make_float4(0.f, 0.f, 0.f, 0.f);
    if (gi == 0) { out[0] = 0.0f; g_sumT2 = 0.0f; }
}

// ---------------------------------------------------------------------------
// Kernel 1 (fat):
//   blocks 0..71   : GEMM G = x @ xT / 2^20 (fp32->bf16 in-reg, mma.sync,
//                    36 upper-tri 64x64 tiles x splitK2, 16 warps/CTA)
//   blocks 72..583 : S gather + sumT2 (pure register, DRAM stream)
// ---------------------------------------------------------------------------
__device__ __forceinline__ uint32_t smem_u32(const void* p) {
    return static_cast<uint32_t>(__cvta_generic_to_shared(p));
}
__device__ __forceinline__ void ldm_x4(uint32_t* d, uint32_t addr) {
    asm volatile("ldmatrix.sync.aligned.m8n8.x4.shared.b16 {%0,%1,%2,%3}, [%4];"
                 : "=r"(d[0]), "=r"(d[1]), "=r"(d[2]), "=r"(d[3]) : "r"(addr));
}
__device__ __forceinline__ void mma_bf16(float* c, const uint32_t* a, uint32_t b0, uint32_t b1) {
    asm volatile("mma.sync.aligned.m16n8k16.row.col.f32.bf16.bf16.f32 "
                 "{%0,%1,%2,%3},{%4,%5,%6,%7},{%8,%9},{%0,%1,%2,%3};"
                 : "+f"(c[0]), "+f"(c[1]), "+f"(c[2]), "+f"(c[3])
                 : "r"(a[0]), "r"(a[1]), "r"(a[2]), "r"(a[3]), "r"(b0), "r"(b1));
}

// smem: A buf b @ b*5120, B buf b @ 10240 + b*5120  (64 rows x 80B padded)
__global__ void __launch_bounds__(512, 2) k_fat(const float* __restrict__ x,
                                                const float* __restrict__ target) {
    __shared__ __align__(16) char sm[20480 + 128];
    const int t = threadIdx.x;
    const int w = t >> 5, l = t & 31;

    if (blockIdx.x < 72) {
        // ---------------- GEMM path ----------------
        const int tile = blockIdx.x % 36;
        const int kz   = (blockIdx.x / 36) * 2048;
        int rem = tile, bi = 0;
        while (rem >= 8 - bi) { rem -= 8 - bi; bi++; }
        const int bj = bi + rem;
        const int m0 = bi * 64, n0 = bj * 64;

        const int wm = (w >> 2) * 16;   // 0..48
        const int wn = (w & 3) * 16;    // 0..48

        float acc[2][4];
        #pragma unroll
        for (int h = 0; h < 2; h++)
            #pragma unroll
            for (int q = 0; q < 4; q++) acc[h][q] = 0.f;

        const int srow = t >> 3;          // staging row 0..63
        const int fc   = (t & 7) * 4;     // float col 0..28
        const int lrow = l & 15;
        const int lkh  = (l >> 4) * 8;

        const float* xa = &x[(m0 + srow) * HW + fc];
        const float* xb = &x[(n0 + srow) * HW + fc];
        const uint32_t sa = smem_u32(sm) + srow * 80 + (t & 7) * 8;
        const uint32_t sb = sa + 10240;

        float4 pa = *reinterpret_cast<const float4*>(xa + kz);
        float4 pb = *reinterpret_cast<const float4*>(xb + kz);

        for (int kc = 0; kc < 64; kc++) {
            const int buf = kc & 1;
            // STS current (convert fp32->bf16, 8B store)
            {
                __nv_bfloat162 q0, q1;
                q0.x = __float2bfloat16(pa.x); q0.y = __float2bfloat16(pa.y);
                q1.x = __float2bfloat16(pa.z); q1.y = __float2bfloat16(pa.w);
                uint2 pk; pk.x = *reinterpret_cast<uint32_t*>(&q0);
                          pk.y = *reinterpret_cast<uint32_t*>(&q1);
                asm volatile("st.shared.v2.b32 [%0], {%1,%2};" ::
                             "r"(sa + buf * 5120), "r"(pk.x), "r"(pk.y));
                q0.x = __float2bfloat16(pb.x); q0.y = __float2bfloat16(pb.y);
                q1.x = __float2bfloat16(pb.z); q1.y = __float2bfloat16(pb.w);
                pk.x = *reinterpret_cast<uint32_t*>(&q0);
                pk.y = *reinterpret_cast<uint32_t*>(&q1);
                asm volatile("st.shared.v2.b32 [%0], {%1,%2};" ::
                             "r"(sb + buf * 5120), "r"(pk.x), "r"(pk.y));
            }
            __syncthreads();
            if (kc < 63) {
                const int kb = kz + (kc + 1) * 32;
                pa = *reinterpret_cast<const float4*>(xa + kb);
                pb = *reinterpret_cast<const float4*>(xb + kb);
            }
            // MMA on current buffer
            const uint32_t Ab = smem_u32(sm) + buf * 5120;
            const uint32_t Bb = Ab + 10240;
            #pragma unroll
            for (int k16 = 0; k16 < 2; k16++) {
                uint32_t afr[4], bfr[4];
                ldm_x4(afr, Ab + (wm + lrow) * 80 + (k16 * 16 + lkh) * 2);
                ldm_x4(bfr, Bb + (wn + lrow) * 80 + (k16 * 16 + lkh) * 2);
                mma_bf16(acc[0], afr, bfr[0], bfr[2]);
                mma_bf16(acc[1], afr, bfr[1], bfr[3]);
            }
        }

        // epilogue: scaled atomic accumulate; mirror for off-diagonal tiles
        const float s = 1.0f / 1048576.0f;
        const int g = l >> 2, cc = (l & 3) * 2;
        const bool mirror = (bi != bj);
        #pragma unroll
        for (int h = 0; h < 2; h++) {
            const int row = m0 + wm + g;
            const int col = n0 + wn + h * 8 + cc;
            const float v0 = acc[h][0] * s;
            const float v1 = acc[h][1] * s;
            const float v2 = acc[h][2] * s;
            const float v3 = acc[h][3] * s;
            atomicAdd(&g_G[row * CH + col],           v0);
            atomicAdd(&g_G[row * CH + col + 1],       v1);
            atomicAdd(&g_G[(row + 8) * CH + col],     v2);
            atomicAdd(&g_G[(row + 8) * CH + col + 1], v3);
            if (mirror) {
                atomicAdd(&g_G[col * CH + row],           v0);
                atomicAdd(&g_G[(col + 1) * CH + row],     v1);
                atomicAdd(&g_G[col * CH + row + 8],       v2);
                atomicAdd(&g_G[(col + 1) * CH + row + 8], v3);
            }
        }
    } else {
        // ---------------- S gather path (no smem in loop) ----------------
        const int r = blockIdx.x - 72;     // 0..511
        float Sreg = 0.f, T2 = 0.f;

        #pragma unroll 1
        for (int jb = 0; jb < 256; jb += 8) {
            float v[8];
            #pragma unroll
            for (int u = 0; u < 8; u++) {
                const int j  = jb + u;
                const int kk = (t - r + j + 512) & 511;
                const int i  = (r - j + 512) & 511;
                v[u] = (kk < 256) ? __ldg(&target[i * 65536 + j * 256 + kk]) : 0.f;
            }
            #pragma unroll
            for (int u = 0; u < 8; u++) {
                Sreg += v[u];
                T2 = fmaf(v[u], v[u], T2);
            }
        }

        g_S[r * CH + t] = Sreg;

        // block-reduce T2
        #pragma unroll
        for (int o = 16; o > 0; o >>= 1)
            T2 += __shfl_xor_sync(0xFFFFFFFFu, T2, o);
        float* red = reinterpret_cast<float*>(sm);
        if (l == 0) red[w] = T2;
        __syncthreads();
        if (w == 0) {
            float z = (l < 16) ? red[l] : 0.f;
            #pragma unroll
            for (int o = 8; o > 0; o >>= 1)
                z += __shfl_xor_sync(0xFFFFFFFFu, z, o);
            if (l == 0) atomicAdd(&g_sumT2, z);
        }
    }
}

// ---------------------------------------------------------------------------
// Kernel 2: combine  loss = (sumT2 - 2*sum(G*S) + sum(mult*G^2)) * SCALE
// ---------------------------------------------------------------------------
__global__ void __launch_bounds__(512) k_combine(float* __restrict__ out) {
    __shared__ float red[512];
    const int t = threadIdx.x;
    const int g = blockIdx.x * 512 + t;     // 262144
    const int r = g >> 9, c = g & 511;
    const float Gv = g_G[g];
    const float Sv = g_S[g];
    const int d = (r - c) & 511;
    const float mult = (float)((d <= 256) ? (256 - d) : (d - 256));
    const float term = fmaf(mult * Gv, Gv, -2.0f * Gv * Sv);

    red[t] = term;
    __syncthreads();
    #pragma unroll
    for (int s = 256; s > 0; s >>= 1) {
        if (t < s) red[t] += red[t + s];
        __syncthreads();
    }
    if (t == 0) atomicAdd(out, red[0] * SCALE);
    if (g == 0) atomicAdd(out, g_sumT2 * SCALE);
}

// ---------------------------------------------------------------------------
extern "C" void kernel_launch(void* const* d_in, const int* in_sizes, int n_in,
                              void* d_out, int out_size) {
    const float* x      = (const float*)d_in[0];   // (1,512,64,64) fp32
    const float* target = (const float*)d_in[1];   // (512,256,256) fp32
    float* out = (float*)d_out;

    k_zero<<<256, 256>>>(out);
    k_fat<<<72 + 512, 512>>>(x, target);
    k_combine<<<512, 512>>>(out);
}

// round 5
// speedup vs baseline: 1.5647x; 1.5647x over previous
#include <cuda_runtime.h>
#include <cuda_bf16.h>
#include <cstdint>

#define CH   512
#define HW   4096
#define SCALE (1.0e6f / 33554432.0f)

__device__ __align__(16) __nv_bfloat16 g_feats[CH * HW];  // 4 MB bf16 feats
__device__ __align__(16) float g_G[CH * CH];              // gram (scaled 1/2^20)
__device__ __align__(16) float g_S[CH * CH];              // S matrix
__device__ __align__(16) float g_T2[CH];                  // per-row sumT2
__device__ unsigned int g_bar;                            // monotonic, never reset

// ---------------------------------------------------------------------------
__device__ __forceinline__ uint32_t smem_u32(const void* p) {
    return static_cast<uint32_t>(__cvta_generic_to_shared(p));
}
__device__ __forceinline__ void cp_async16(uint32_t dst, const void* src) {
    asm volatile("cp.async.cg.shared.global [%0], [%1], 16;\n" :: "r"(dst), "l"(src));
}
__device__ __forceinline__ void ldm_x4(uint32_t* d, uint32_t addr) {
    asm volatile("ldmatrix.sync.aligned.m8n8.x4.shared.b16 {%0,%1,%2,%3}, [%4];"
                 : "=r"(d[0]), "=r"(d[1]), "=r"(d[2]), "=r"(d[3]) : "r"(addr));
}
__device__ __forceinline__ void mma_bf16(float* c, const uint32_t* a, uint32_t b0, uint32_t b1) {
    asm volatile("mma.sync.aligned.m16n8k16.row.col.f32.bf16.bf16.f32 "
                 "{%0,%1,%2,%3},{%4,%5,%6,%7},{%8,%9},{%0,%1,%2,%3};"
                 : "+f"(c[0]), "+f"(c[1]), "+f"(c[2]), "+f"(c[3])
                 : "r"(a[0]), "r"(a[1]), "r"(a[2]), "r"(a[3]), "r"(b0), "r"(b1));
}

// smem: A[2][64][144B] @0, B[2][64][144B] @18432  (GEMM);  red[] reuse (S path)
__global__ void __launch_bounds__(256) k_fat(const float* __restrict__ x,
                                             const float* __restrict__ target,
                                             float* __restrict__ out) {
    __shared__ __align__(16) char sm[36864 + 64];
    const int t = threadIdx.x;
    const int w = t >> 5, l = t & 31;

    if (blockIdx.x < 72) {
        // ============ Phase 1: convert x -> bf16 g_feats, zero G ============
        const int gi = blockIdx.x * 256 + t;        // 0..18431
        for (int idx = gi; idx < 524288; idx += 18432) {
            float4 v = reinterpret_cast<const float4*>(x)[idx];
            __nv_bfloat162 p0, p1;
            p0.x = __float2bfloat16(v.x); p0.y = __float2bfloat16(v.y);
            p1.x = __float2bfloat16(v.z); p1.y = __float2bfloat16(v.w);
            uint2 pk;
            pk.x = *reinterpret_cast<uint32_t*>(&p0);
            pk.y = *reinterpret_cast<uint32_t*>(&p1);
            reinterpret_cast<uint2*>(g_feats)[idx] = pk;
        }
        for (int idx = gi; idx < 65536; idx += 18432)
            reinterpret_cast<float4*>(g_G)[idx] = make_float4(0.f, 0.f, 0.f, 0.f);
        if (gi == 0) out[0] = 0.0f;

        // ============ sub-grid barrier among the 72 GEMM CTAs ============
        __threadfence();
        __syncthreads();
        if (t == 0) {
            unsigned old = atomicAdd(&g_bar, 1u);
            unsigned tgt = old - (old % 72u) + 72u;
            unsigned cur;
            do {
                asm volatile("ld.acquire.gpu.u32 %0, [%1];" : "=r"(cur) : "l"(&g_bar));
            } while (cur < tgt);
        }
        __syncthreads();

        // ============ Phase 2: GEMM (R2-proven mainloop, 8 warps) ============
        const int tile = blockIdx.x % 36;
        const int kz   = (blockIdx.x / 36) * 2048;
        int rem = tile, bi = 0;
        while (rem >= 8 - bi) { rem -= 8 - bi; bi++; }
        const int bj = bi + rem;
        const int m0 = bi * 64, n0 = bj * 64;

        const int wm = (w >> 2) * 32;   // 0,32
        const int wn = (w & 3) * 16;    // 0..48

        float acc[2][2][4];
        #pragma unroll
        for (int a = 0; a < 2; a++)
          #pragma unroll
          for (int h = 0; h < 2; h++)
            #pragma unroll
            for (int q = 0; q < 4; q++) acc[a][h][q] = 0.f;

        const int lr = t >> 3;           // 0..31
        const int lc = (t & 7) * 8;      // bf16 col (16B chunks)
        const int lrow = l & 15;
        const int lkh  = (l >> 4) * 8;
        const uint32_t smA = smem_u32(sm);
        const uint32_t smB = smA + 18432;

        auto load_stage = [&](int ks, int buf) {
            const int kb = kz + ks * 64;
            #pragma unroll
            for (int p = 0; p < 2; p++) {
                const int row = lr + p * 32;
                cp_async16(smA + buf * 9216 + row * 144 + lc * 2,
                           &g_feats[(m0 + row) * HW + kb + lc]);
                cp_async16(smB + buf * 9216 + row * 144 + lc * 2,
                           &g_feats[(n0 + row) * HW + kb + lc]);
            }
            asm volatile("cp.async.commit_group;\n" ::: "memory");
        };

        load_stage(0, 0);
        for (int ks = 0; ks < 32; ks++) {
            const int buf = ks & 1;
            if (ks < 31) {
                load_stage(ks + 1, buf ^ 1);
                asm volatile("cp.async.wait_group 1;\n" ::: "memory");
            } else {
                asm volatile("cp.async.wait_group 0;\n" ::: "memory");
            }
            __syncthreads();

            #pragma unroll
            for (int k16 = 0; k16 < 4; k16++) {
                uint32_t afr[2][4], bfr[4];
                #pragma unroll
                for (int mt = 0; mt < 2; mt++)
                    ldm_x4(afr[mt], smA + buf * 9216 + (wm + mt * 16 + lrow) * 144
                                        + (k16 * 16 + lkh) * 2);
                ldm_x4(bfr, smB + buf * 9216 + (wn + lrow) * 144
                                + (k16 * 16 + lkh) * 2);
                #pragma unroll
                for (int mt = 0; mt < 2; mt++) {
                    mma_bf16(acc[mt][0], afr[mt], bfr[0], bfr[2]);
                    mma_bf16(acc[mt][1], afr[mt], bfr[1], bfr[3]);
                }
            }
            __syncthreads();
        }

        // epilogue: split-K atomics, scaled; mirror off-diagonal tiles
        const float s = 1.0f / 1048576.0f;
        const int g2 = l >> 2, cc = (l & 3) * 2;
        const bool mirror = (bi != bj);
        #pragma unroll
        for (int mt = 0; mt < 2; mt++)
          #pragma unroll
          for (int h = 0; h < 2; h++) {
            const int row = m0 + wm + mt * 16 + g2;
            const int col = n0 + wn + h * 8 + cc;
            const float v0 = acc[mt][h][0] * s;
            const float v1 = acc[mt][h][1] * s;
            const float v2 = acc[mt][h][2] * s;
            const float v3 = acc[mt][h][3] * s;
            atomicAdd(&g_G[row * CH + col],           v0);
            atomicAdd(&g_G[row * CH + col + 1],       v1);
            atomicAdd(&g_G[(row + 8) * CH + col],     v2);
            atomicAdd(&g_G[(row + 8) * CH + col + 1], v3);
            if (mirror) {
                atomicAdd(&g_G[col * CH + row],           v0);
                atomicAdd(&g_G[(col + 1) * CH + row],     v1);
                atomicAdd(&g_G[col * CH + row + 8],       v2);
                atomicAdd(&g_G[(col + 1) * CH + row + 8], v3);
            }
          }
    } else {
        // ============ S-stream: every lane loads exactly once per j ============
        const int r = blockIdx.x - 72;          // 0..511
        const int base = (t - r) & 511;
        float Slo = 0.f, Shi = 0.f, T2 = 0.f;

        #pragma unroll 1
        for (int jb = 0; jb < 256; jb += 8) {
            float v[8]; int hi[8];
            #pragma unroll
            for (int u = 0; u < 8; u++) {
                const int j  = jb + u;
                const int kk = (base + j) & 511;
                const int i  = (r - j) & 511;
                hi[u] = kk >> 8;
                v[u] = __ldg(&target[(i << 16) + (j << 8) + (kk & 255)]);
            }
            #pragma unroll
            for (int u = 0; u < 8; u++) {
                T2 = fmaf(v[u], v[u], T2);
                if (hi[u]) Shi += v[u]; else Slo += v[u];
            }
        }

        g_S[r * CH + t]       = Slo;
        g_S[r * CH + t + 256] = Shi;

        // block-reduce T2 -> g_T2[r]
        #pragma unroll
        for (int o = 16; o > 0; o >>= 1)
            T2 += __shfl_xor_sync(0xFFFFFFFFu, T2, o);
        float* red = reinterpret_cast<float*>(sm);
        if (l == 0) red[w] = T2;
        __syncthreads();
        if (t == 0) {
            float z = 0.f;
            #pragma unroll
            for (int ww = 0; ww < 8; ww++) z += red[ww];
            g_T2[r] = z;
        }
    }
}

// ---------------------------------------------------------------------------
// Kernel B: loss = sum( mult*G^2 - 2*G*S ) * SCALE + sum(T2) * SCALE
// ---------------------------------------------------------------------------
__global__ void __launch_bounds__(512) k_combine(float* __restrict__ out) {
    __shared__ float red[512];
    const int t = threadIdx.x;
    const int g = blockIdx.x * 512 + t;     // 262144
    const int r = g >> 9, c = g & 511;
    const float Gv = g_G[g];
    const float Sv = g_S[g];
    const int d = (r - c) & 511;
    const float mult = (float)((d <= 256) ? (256 - d) : (d - 256));
    float term = fmaf(mult * Gv, Gv, -2.0f * Gv * Sv);
    if (t == 0) term += g_T2[blockIdx.x];

    red[t] = term;
    __syncthreads();
    #pragma unroll
    for (int s = 256; s > 0; s >>= 1) {
        if (t < s) red[t] += red[t + s];
        __syncthreads();
    }
    if (t == 0) atomicAdd(out, red[0] * SCALE);
}

// ---------------------------------------------------------------------------
extern "C" void kernel_launch(void* const* d_in, const int* in_sizes, int n_in,
                              void* d_out, int out_size) {
    const float* x      = (const float*)d_in[0];   // (1,512,64,64) fp32
    const float* target = (const float*)d_in[1];   // (512,256,256) fp32
    float* out = (float*)d_out;

    k_fat<<<72 + 512, 256>>>(x, target, out);
    k_combine<<<512, 512>>>(out);
}

// round 6
// speedup vs baseline: 1.5864x; 1.0139x over previous
#include <cuda_runtime.h>
#include <cuda_bf16.h>
#include <cstdint>

#define CH   512
#define HW   4096
#define SCALE (1.0e6f / 33554432.0f)
#define NCTA 584

__device__ __align__(16) __nv_bfloat16 g_feats[CH * HW];  // 4 MB bf16 feats
__device__ __align__(16) float g_G[CH * CH];              // gram (scaled 1/2^20)
__device__ __align__(16) float g_S[CH * CH];              // S matrix
__device__ __align__(16) float g_T2[CH];                  // per-row sumT2
__device__ unsigned int g_barA;   // 72-CTA convert barrier (monotonic)
__device__ unsigned int g_barB;   // 584-CTA full barrier  (monotonic)

// ---------------------------------------------------------------------------
__device__ __forceinline__ uint32_t smem_u32(const void* p) {
    return static_cast<uint32_t>(__cvta_generic_to_shared(p));
}
__device__ __forceinline__ void cp_async16(uint32_t dst, const void* src) {
    asm volatile("cp.async.cg.shared.global [%0], [%1], 16;\n" :: "r"(dst), "l"(src));
}
__device__ __forceinline__ void ldm_x4(uint32_t* d, uint32_t addr) {
    asm volatile("ldmatrix.sync.aligned.m8n8.x4.shared.b16 {%0,%1,%2,%3}, [%4];"
                 : "=r"(d[0]), "=r"(d[1]), "=r"(d[2]), "=r"(d[3]) : "r"(addr));
}
__device__ __forceinline__ void mma_bf16(float* c, const uint32_t* a, uint32_t b0, uint32_t b1) {
    asm volatile("mma.sync.aligned.m16n8k16.row.col.f32.bf16.bf16.f32 "
                 "{%0,%1,%2,%3},{%4,%5,%6,%7},{%8,%9},{%0,%1,%2,%3};"
                 : "+f"(c[0]), "+f"(c[1]), "+f"(c[2]), "+f"(c[3])
                 : "r"(a[0]), "r"(a[1]), "r"(a[2]), "r"(a[3]), "r"(b0), "r"(b1));
}
// monotonic barrier: each launch adds exactly N to ctr; works across graph replays
__device__ __forceinline__ void mono_barrier(unsigned int* ctr, unsigned N) {
    unsigned old = atomicAdd(ctr, 1u);
    unsigned tgt = old - (old % N) + N;
    unsigned cur;
    do {
        __nanosleep(64);
        asm volatile("ld.acquire.gpu.u32 %0, [%1];" : "=r"(cur) : "l"(ctr));
    } while (cur < tgt);
}

// smem: GEMM A[2][64][144B] @0, B[2][64][144B] @18432;  S path reuses front
__global__ void __launch_bounds__(256, 4) k_all(const float* __restrict__ x,
                                                const float* __restrict__ target,
                                                float* __restrict__ out) {
    __shared__ __align__(16) char sm[36864 + 64];
    const int t = threadIdx.x;
    const int w = t >> 5, l = t & 31;
    const int bid = blockIdx.x;

    if (bid < 72) {
        // ============ Phase 1: convert x -> bf16, zero G ============
        const int gi = bid * 256 + t;              // 0..18431
        for (int idx = gi; idx < 524288; idx += 18432) {
            float4 v = reinterpret_cast<const float4*>(x)[idx];
            __nv_bfloat162 p0, p1;
            p0.x = __float2bfloat16(v.x); p0.y = __float2bfloat16(v.y);
            p1.x = __float2bfloat16(v.z); p1.y = __float2bfloat16(v.w);
            uint2 pk;
            pk.x = *reinterpret_cast<uint32_t*>(&p0);
            pk.y = *reinterpret_cast<uint32_t*>(&p1);
            reinterpret_cast<uint2*>(g_feats)[idx] = pk;
        }
        for (int idx = gi; idx < 65536; idx += 18432)
            reinterpret_cast<float4*>(g_G)[idx] = make_float4(0.f, 0.f, 0.f, 0.f);
        if (gi == 0) out[0] = 0.0f;

        __threadfence();
        __syncthreads();
        if (t == 0) mono_barrier(&g_barA, 72u);
        __syncthreads();

        // ============ Phase 2: GEMM (upper-tri 64x64 tiles, splitK 2) ============
        const int tile = bid % 36;
        const int kz   = (bid / 36) * 2048;
        int rem = tile, bi = 0;
        while (rem >= 8 - bi) { rem -= 8 - bi; bi++; }
        const int bj = bi + rem;
        const int m0 = bi * 64, n0 = bj * 64;

        const int wm = (w >> 2) * 32;
        const int wn = (w & 3) * 16;

        float acc[2][2][4];
        #pragma unroll
        for (int a = 0; a < 2; a++)
          #pragma unroll
          for (int h = 0; h < 2; h++)
            #pragma unroll
            for (int q = 0; q < 4; q++) acc[a][h][q] = 0.f;

        const int lr = t >> 3;
        const int lc = (t & 7) * 8;
        const int lrow = l & 15;
        const int lkh  = (l >> 4) * 8;
        const uint32_t smA = smem_u32(sm);
        const uint32_t smB = smA + 18432;

        auto load_stage = [&](int ks, int buf) {
            const int kb = kz + ks * 64;
            #pragma unroll
            for (int p = 0; p < 2; p++) {
                const int row = lr + p * 32;
                cp_async16(smA + buf * 9216 + row * 144 + lc * 2,
                           &g_feats[(m0 + row) * HW + kb + lc]);
                cp_async16(smB + buf * 9216 + row * 144 + lc * 2,
                           &g_feats[(n0 + row) * HW + kb + lc]);
            }
            asm volatile("cp.async.commit_group;\n" ::: "memory");
        };

        load_stage(0, 0);
        for (int ks = 0; ks < 32; ks++) {
            const int buf = ks & 1;
            if (ks < 31) {
                load_stage(ks + 1, buf ^ 1);
                asm volatile("cp.async.wait_group 1;\n" ::: "memory");
            } else {
                asm volatile("cp.async.wait_group 0;\n" ::: "memory");
            }
            __syncthreads();

            #pragma unroll
            for (int k16 = 0; k16 < 4; k16++) {
                uint32_t afr[2][4], bfr[4];
                #pragma unroll
                for (int mt = 0; mt < 2; mt++)
                    ldm_x4(afr[mt], smA + buf * 9216 + (wm + mt * 16 + lrow) * 144
                                        + (k16 * 16 + lkh) * 2);
                ldm_x4(bfr, smB + buf * 9216 + (wn + lrow) * 144
                                + (k16 * 16 + lkh) * 2);
                #pragma unroll
                for (int mt = 0; mt < 2; mt++) {
                    mma_bf16(acc[mt][0], afr[mt], bfr[0], bfr[2]);
                    mma_bf16(acc[mt][1], afr[mt], bfr[1], bfr[3]);
                }
            }
            __syncthreads();
        }

        const float s = 1.0f / 1048576.0f;
        const int g2 = l >> 2, cc = (l & 3) * 2;
        const bool mirror = (bi != bj);
        #pragma unroll
        for (int mt = 0; mt < 2; mt++)
          #pragma unroll
          for (int h = 0; h < 2; h++) {
            const int row = m0 + wm + mt * 16 + g2;
            const int col = n0 + wn + h * 8 + cc;
            const float v0 = acc[mt][h][0] * s;
            const float v1 = acc[mt][h][1] * s;
            const float v2 = acc[mt][h][2] * s;
            const float v3 = acc[mt][h][3] * s;
            atomicAdd(&g_G[row * CH + col],           v0);
            atomicAdd(&g_G[row * CH + col + 1],       v1);
            atomicAdd(&g_G[(row + 8) * CH + col],     v2);
            atomicAdd(&g_G[(row + 8) * CH + col + 1], v3);
            if (mirror) {
                atomicAdd(&g_G[col * CH + row],           v0);
                atomicAdd(&g_G[(col + 1) * CH + row],     v1);
                atomicAdd(&g_G[col * CH + row + 8],       v2);
                atomicAdd(&g_G[(col + 1) * CH + row + 8], v3);
            }
          }
    } else {
        // ============ S-stream: one coalesced load per lane per j ============
        const int r = bid - 72;                 // 0..511
        const int base = (t - r) & 511;
        float Slo = 0.f, Shi = 0.f, T2 = 0.f;

        #pragma unroll 1
        for (int jb = 0; jb < 256; jb += 8) {
            float v[8]; int hi[8];
            #pragma unroll
            for (int u = 0; u < 8; u++) {
                const int j  = jb + u;
                const int kk = (base + j) & 511;
                const int i  = (r - j) & 511;
                hi[u] = kk >> 8;
                v[u] = __ldg(&target[(i << 16) + (j << 8) + (kk & 255)]);
            }
            #pragma unroll
            for (int u = 0; u < 8; u++) {
                T2 = fmaf(v[u], v[u], T2);
                if (hi[u]) Shi += v[u]; else Slo += v[u];
            }
        }

        g_S[r * CH + t]       = Slo;
        g_S[r * CH + t + 256] = Shi;

        #pragma unroll
        for (int o = 16; o > 0; o >>= 1)
            T2 += __shfl_xor_sync(0xFFFFFFFFu, T2, o);
        float* red = reinterpret_cast<float*>(sm);
        if (l == 0) red[w] = T2;
        __syncthreads();
        if (t == 0) {
            float z = 0.f;
            #pragma unroll
            for (int ww = 0; ww < 8; ww++) z += red[ww];
            g_T2[r] = z;
        }
    }

    // ============ full-grid barrier, then fused combine ============
    __threadfence();
    __syncthreads();
    float* redc = reinterpret_cast<float*>(sm);
    if (t == 0) mono_barrier(&g_barB, NCTA);
    __syncthreads();

    float term = 0.f;
    for (int idx = bid * 256 + t; idx < 262144; idx += NCTA * 256) {
        const int rr = idx >> 9, cc2 = idx & 511;
        const float Gv = g_G[idx];
        const float Sv = g_S[idx];
        const int d = (rr - cc2) & 511;
        const float mult = (float)((d <= 256) ? (256 - d) : (d - 256));
        term += fmaf(mult * Gv, Gv, -2.0f * Gv * Sv);
        if (idx < 512) term += g_T2[idx];
    }
    #pragma unroll
    for (int o = 16; o > 0; o >>= 1)
        term += __shfl_xor_sync(0xFFFFFFFFu, term, o);
    if (l == 0) redc[w] = term;
    __syncthreads();
    if (t == 0) {
        float z = 0.f;
        #pragma unroll
        for (int ww = 0; ww < 8; ww++) z += redc[ww];
        atomicAdd(out, z * SCALE);
    }
}

// ---------------------------------------------------------------------------
extern "C" void kernel_launch(void* const* d_in, const int* in_sizes, int n_in,
                              void* d_out, int out_size) {
    const float* x      = (const float*)d_in[0];   // (1,512,64,64) fp32
    const float* target = (const float*)d_in[1];   // (512,256,256) fp32
    float* out = (float*)d_out;

    k_all<<<NCTA, 256>>>(x, target, out);
}

// round 7
// speedup vs baseline: 1.7498x; 1.1030x over previous
#include <cuda_runtime.h>
#include <cuda_bf16.h>
#include <cstdint>

#define CH    512
#define HW    4096
#define SCALE (1.0e6f / 33554432.0f)
#define NGEMM 72
#define NS    512
#define NCTA  (NGEMM + NS)

__device__ __align__(16) __nv_bfloat16 g_feats[CH * HW];  // 4 MB bf16 feats
__device__ __align__(16) float g_G[CH * CH];              // gram (scaled 1/2^20)
__device__ unsigned int g_barA;   // convert barrier (monotonic, +NCTA per launch)
__device__ unsigned int g_barB;   // full barrier    (monotonic, +NCTA per launch)

// ---------------------------------------------------------------------------
__device__ __forceinline__ uint32_t smem_u32(const void* p) {
    return static_cast<uint32_t>(__cvta_generic_to_shared(p));
}
__device__ __forceinline__ void cp_async16(uint32_t dst, const void* src) {
    asm volatile("cp.async.cg.shared.global [%0], [%1], 16;\n" :: "r"(dst), "l"(src));
}
template <int N>
__device__ __forceinline__ void cp_wait() {
    asm volatile("cp.async.wait_group %0;\n" :: "n"(N) : "memory");
}
__device__ __forceinline__ void ldm_x4(uint32_t* d, uint32_t addr) {
    asm volatile("ldmatrix.sync.aligned.m8n8.x4.shared.b16 {%0,%1,%2,%3}, [%4];"
                 : "=r"(d[0]), "=r"(d[1]), "=r"(d[2]), "=r"(d[3]) : "r"(addr));
}
__device__ __forceinline__ void mma_bf16(float* c, const uint32_t* a, uint32_t b0, uint32_t b1) {
    asm volatile("mma.sync.aligned.m16n8k16.row.col.f32.bf16.bf16.f32 "
                 "{%0,%1,%2,%3},{%4,%5,%6,%7},{%8,%9},{%0,%1,%2,%3};"
                 : "+f"(c[0]), "+f"(c[1]), "+f"(c[2]), "+f"(c[3])
                 : "r"(a[0]), "r"(a[1]), "r"(a[2]), "r"(a[3]), "r"(b0), "r"(b1));
}
__device__ __forceinline__ void spin_to(unsigned int* ctr, unsigned tgt) {
    unsigned cur;
    do {
        __nanosleep(64);
        asm volatile("ld.acquire.gpu.u32 %0, [%1];" : "=r"(cur) : "l"(ctr));
    } while (cur < tgt);
}

// smem: GEMM A[2][64][144B]@0, B[2][64][144B]@18432 (36864B total)
//       S-path: ring 4 stages x 8KB @0 (32768B); red[] reuse @0 post-barrier
__global__ void __launch_bounds__(256, 4) k_all(const float* __restrict__ x,
                                                const float* __restrict__ target,
                                                float* __restrict__ out) {
    __shared__ __align__(16) char sm[36928];
    const int t = threadIdx.x;
    const int w = t >> 5, l = t & 31;
    const int bid = blockIdx.x;

    // ============ Phase 1: convert x -> bf16 (all CTAs), zero G ============
    const int gi = bid * 256 + t;                  // 0..149503
    for (int idx = gi; idx < 524288; idx += NCTA * 256) {
        float4 v = reinterpret_cast<const float4*>(x)[idx];
        __nv_bfloat162 p0, p1;
        p0.x = __float2bfloat16(v.x); p0.y = __float2bfloat16(v.y);
        p1.x = __float2bfloat16(v.z); p1.y = __float2bfloat16(v.w);
        uint2 pk;
        pk.x = *reinterpret_cast<uint32_t*>(&p0);
        pk.y = *reinterpret_cast<uint32_t*>(&p1);
        reinterpret_cast<uint2*>(g_feats)[idx] = pk;
    }
    if (gi < 65536)
        reinterpret_cast<float4*>(g_G)[gi] = make_float4(0.f, 0.f, 0.f, 0.f);
    if (gi == 0) out[0] = 0.0f;

    __threadfence();
    __syncthreads();
    if (t == 0) {
        unsigned old = atomicAdd(&g_barA, 1u);
        if (bid < NGEMM) {                  // only GEMM CTAs wait for convert
            unsigned tgt = old - (old % NCTA) + NCTA;
            spin_to(&g_barA, tgt);
        }
    }

    if (bid < NGEMM) {
        // ============ GEMM: upper-tri 64x64 tiles, splitK 2 (proven) ============
        __syncthreads();
        const int tile = bid % 36;
        const int kz   = (bid / 36) * 2048;
        int rem = tile, bi = 0;
        while (rem >= 8 - bi) { rem -= 8 - bi; bi++; }
        const int bj = bi + rem;
        const int m0 = bi * 64, n0 = bj * 64;

        const int wm = (w >> 2) * 32;
        const int wn = (w & 3) * 16;

        float acc[2][2][4];
        #pragma unroll
        for (int a = 0; a < 2; a++)
          #pragma unroll
          for (int h = 0; h < 2; h++)
            #pragma unroll
            for (int q = 0; q < 4; q++) acc[a][h][q] = 0.f;

        const int lr = t >> 3;
        const int lc = (t & 7) * 8;
        const int lrow = l & 15;
        const int lkh  = (l >> 4) * 8;
        const uint32_t smA = smem_u32(sm);
        const uint32_t smB = smA + 18432;

        auto load_stage = [&](int ks, int buf) {
            const int kb = kz + ks * 64;
            #pragma unroll
            for (int p = 0; p < 2; p++) {
                const int row = lr + p * 32;
                cp_async16(smA + buf * 9216 + row * 144 + lc * 2,
                           &g_feats[(m0 + row) * HW + kb + lc]);
                cp_async16(smB + buf * 9216 + row * 144 + lc * 2,
                           &g_feats[(n0 + row) * HW + kb + lc]);
            }
            asm volatile("cp.async.commit_group;\n" ::: "memory");
        };

        load_stage(0, 0);
        for (int ks = 0; ks < 32; ks++) {
            const int buf = ks & 1;
            if (ks < 31) {
                load_stage(ks + 1, buf ^ 1);
                cp_wait<1>();
            } else {
                cp_wait<0>();
            }
            __syncthreads();

            #pragma unroll
            for (int k16 = 0; k16 < 4; k16++) {
                uint32_t afr[2][4], bfr[4];
                #pragma unroll
                for (int mt = 0; mt < 2; mt++)
                    ldm_x4(afr[mt], smA + buf * 9216 + (wm + mt * 16 + lrow) * 144
                                        + (k16 * 16 + lkh) * 2);
                ldm_x4(bfr, smB + buf * 9216 + (wn + lrow) * 144
                                + (k16 * 16 + lkh) * 2);
                #pragma unroll
                for (int mt = 0; mt < 2; mt++) {
                    mma_bf16(acc[mt][0], afr[mt], bfr[0], bfr[2]);
                    mma_bf16(acc[mt][1], afr[mt], bfr[1], bfr[3]);
                }
            }
            __syncthreads();
        }

        const float s = 1.0f / 1048576.0f;
        const int g2 = l >> 2, cc = (l & 3) * 2;
        const bool mirror = (bi != bj);
        #pragma unroll
        for (int mt = 0; mt < 2; mt++)
          #pragma unroll
          for (int h = 0; h < 2; h++) {
            const int row = m0 + wm + mt * 16 + g2;
            const int col = n0 + wn + h * 8 + cc;
            const float v0 = acc[mt][h][0] * s;
            const float v1 = acc[mt][h][1] * s;
            const float v2 = acc[mt][h][2] * s;
            const float v3 = acc[mt][h][3] * s;
            atomicAdd(&g_G[row * CH + col],           v0);
            atomicAdd(&g_G[row * CH + col + 1],       v1);
            atomicAdd(&g_G[(row + 8) * CH + col],     v2);
            atomicAdd(&g_G[(row + 8) * CH + col + 1], v3);
            if (mirror) {
                atomicAdd(&g_G[col * CH + row],           v0);
                atomicAdd(&g_G[(col + 1) * CH + row],     v1);
                atomicAdd(&g_G[col * CH + row + 8],       v2);
                atomicAdd(&g_G[(col + 1) * CH + row + 8], v3);
            }
          }

        __threadfence();
        __syncthreads();
        if (t == 0) atomicAdd(&g_barB, 1u);      // arrive, no spin, done
        return;
    }

    // ============ S-stream: cp.async ring, 4 stages x 8 rows(8KB) ============
    const int r    = bid - NGEMM;            // 0..511
    const int base = (t - r) & 511;
    const int xr   = t >> 5;                 // row within stage (0..7)
    const int lane = t & 31;
    const uint32_t stg_u = smem_u32(sm);
    float* stg = reinterpret_cast<float*>(sm);

    float Slo = 0.f, Shi = 0.f, T2a = 0.f, T2b = 0.f;

    auto issue = [&](int s) {
        const int j = s * 8 + xr;
        const int i = (r - j) & 511;
        const float* src = target + (i << 16) + (j << 8) + lane * 8;
        const uint32_t dst = stg_u + (s & 3) * 8192 + xr * 1024 + lane * 32;
        cp_async16(dst, src);
        cp_async16(dst + 16, src + 4);
        asm volatile("cp.async.commit_group;\n" ::: "memory");
    };

    issue(0); issue(1); issue(2);
    #pragma unroll 1
    for (int s = 0; s < 32; s++) {
        if (s < 30)       cp_wait<2>();
        else if (s == 30) cp_wait<1>();
        else              cp_wait<0>();
        __syncthreads();                 // stage s visible to all; slot (s-1)&3 free
        if (s < 29) issue(s + 3);

        const float* buf = stg + (s & 3) * 2048;
        int kk = (base + s * 8) & 511;
        #pragma unroll
        for (int xx = 0; xx < 8; xx++) {
            const float v = buf[xx * 256 + (kk & 255)];
            if (xx & 1) T2b = fmaf(v, v, T2b); else T2a = fmaf(v, v, T2a);
            if (kk >> 8) Shi += v; else Slo += v;
            kk = (kk + 1) & 511;
        }
    }

    // ============ full barrier, then in-place combine vs G row r ============
    __syncthreads();
    if (t == 0) {
        unsigned old = atomicAdd(&g_barB, 1u);
        unsigned tgt = old - (old % NCTA) + NCTA;
        spin_to(&g_barB, tgt);
    }
    __syncthreads();

    const float Gl = g_G[r * CH + t];
    const float Gh = g_G[r * CH + t + 256];
    const int d1 = (r - t) & 511;
    const int d2 = (r - t - 256) & 511;
    const float m1 = (float)((d1 <= 256) ? 256 - d1 : d1 - 256);
    const float m2 = (float)((d2 <= 256) ? 256 - d2 : d2 - 256);
    float term = fmaf(m1 * Gl, Gl, -2.0f * Gl * Slo)
               + fmaf(m2 * Gh, Gh, -2.0f * Gh * Shi)
               + T2a + T2b;

    #pragma unroll
    for (int o = 16; o > 0; o >>= 1)
        term += __shfl_xor_sync(0xFFFFFFFFu, term, o);
    float* red = reinterpret_cast<float*>(sm);
    if (l == 0) red[w] = term;
    __syncthreads();
    if (t == 0) {
        float z = 0.f;
        #pragma unroll
        for (int ww = 0; ww < 8; ww++) z += red[ww];
        atomicAdd(out, z * SCALE);
    }
}

// ---------------------------------------------------------------------------
extern "C" void kernel_launch(void* const* d_in, const int* in_sizes, int n_in,
                              void* d_out, int out_size) {
    const float* x      = (const float*)d_in[0];   // (1,512,64,64) fp32
    const float* target = (const float*)d_in[1];   // (512,256,256) fp32
    float* out = (float*)d_out;

    k_all<<<NCTA, 256>>>(x, target, out);
}